// round 7
// baseline (speedup 1.0000x reference)
#include <cuda_runtime.h>
#include <cuda_bf16.h>
#include <cstdint>

// adaptive_avg_pool2d(x[32,2048,28,28], 7) -> out[32,49,2048]
// linspace(0,28,8) = 0,4,...,28 => exact uniform 4x4 windows.
//
// R7: cp.async (LDGSTS) to get MLP=7 AND 64 warps/SM at once. R6 showed the
// register file forces an MLP/occupancy trade when batched loads live in
// registers (38 regs -> 48 warps, occ 67%, DRAM 82%). cp.async copies the
// raw plane global->smem with zero register residency: regs ~24, 8 blocks/SM,
// in-flight ~57KB/SM. Phase 2 sums each 4x4 bin from the raw stage with
// 4 x LDS.128. Grid stays 8192 short blocks.

#define CCH    2048
#define HW     784
#define NQ     196       // 16B chunks per 28x28 plane
#define TILE_C 8
#define ACC_STRIDE 57    // odd stride: conflict-free transposed readout
#define STG_F  784       // floats per warp raw stage (3136 B, 16B multiple)

__global__ __launch_bounds__(256, 8)
void upp_pool_kernel(const float* __restrict__ x, float* __restrict__ out) {
    __shared__ __align__(16) float stage[8 * STG_F];   // 25088 B raw planes
    __shared__ float acc[TILE_C * ACC_STRIDE];         // 1824 B

    const int b    = blockIdx.y;
    const int c0   = blockIdx.x * TILE_C;
    const int tid  = threadIdx.x;
    const int warp = tid >> 5;     // = c_local: one channel per warp
    const int lane = tid & 31;

    const float* __restrict__ plane =
        x + ((size_t)(b * CCH + c0 + warp)) * HW;
    float* __restrict__ ws = &stage[warp * STG_F];
    const uint32_t sbase =
        (uint32_t)__cvta_generic_to_shared(ws) + (uint32_t)lane * 16u;

    // Phase 1: 7 x cp.async.cg 16B per lane, global->smem, no registers.
    // Chunk q = lane + 32k; q=192..195 only for lane<4.
    #pragma unroll
    for (int k = 0; k < 6; ++k) {
        asm volatile("cp.async.cg.shared.global [%0], [%1], 16;\n"
                     :: "r"(sbase + 512u * k),
                        "l"(plane + lane * 4 + 128 * k)
                     : "memory");
    }
    if (lane < 4) {
        asm volatile("cp.async.cg.shared.global [%0], [%1], 16;\n"
                     :: "r"(sbase + 512u * 6),
                        "l"(plane + lane * 4 + 128 * 6)
                     : "memory");
    }
    asm volatile("cp.async.commit_group;\n"
                 "cp.async.wait_group 0;\n" ::: "memory");
    __syncwarp();

    // Phase 2: bin (i,j) = sum of rows 4i..4i+3, cols 4j..4j+3
    //          = 4 x LDS.128 at float offsets (4i+r)*28 + 4j  (16B aligned)
    {
        const int i = lane / 7, j = lane % 7;
        const float4* r = reinterpret_cast<const float4*>(ws + 112 * i + 4 * j);
        const float4 a = r[0], bb = r[7], c = r[14], d = r[21];
        acc[warp * ACC_STRIDE + lane] =
            ((a.x + a.y + a.z + a.w) + (bb.x + bb.y + bb.z + bb.w) +
             (c.x + c.y + c.z + c.w) + (d.x + d.y + d.z + d.w)) * 0.0625f;
    }
    if (lane < 17) {
        const int bn = lane + 32;
        const int i = bn / 7, j = bn % 7;
        const float4* r = reinterpret_cast<const float4*>(ws + 112 * i + 4 * j);
        const float4 a = r[0], bb = r[7], c = r[14], d = r[21];
        acc[warp * ACC_STRIDE + bn] =
            ((a.x + a.y + a.z + a.w) + (bb.x + bb.y + bb.z + bb.w) +
             (c.x + c.y + c.z + c.w) + (d.x + d.y + d.z + d.w)) * 0.0625f;
    }
    __syncthreads();

    // out[b, p, c0+c] = acc[c*57 + p]; 8 contiguous floats per p-row
    float* __restrict__ ob = out + (size_t)b * 49 * CCH + c0;
    #pragma unroll
    for (int i = tid; i < 49 * TILE_C; i += 256) {
        const int p = i >> 3;              // 0..48
        const int c = i & (TILE_C - 1);    // 0..7
        ob[p * CCH + c] = acc[c * ACC_STRIDE + p];
    }
}

extern "C" void kernel_launch(void* const* d_in, const int* in_sizes, int n_in,
                              void* d_out, int out_size) {
    const float* x = (const float*)d_in[0];
    float* out = (float*)d_out;
    dim3 grid(CCH / TILE_C, 32);   // (256, 32) = 8192 short blocks
    upp_pool_kernel<<<grid, 256>>>(x, out);
}

// round 8
// speedup vs baseline: 1.0164x; 1.0164x over previous
#include <cuda_runtime.h>
#include <cuda_bf16.h>
#include <cstdint>

// adaptive_avg_pool2d(x[32,2048,28,28], 7) -> out[32,49,2048]
// linspace(0,28,8) = 0,4,...,28 => exact uniform 4x4 windows.
//
// R8: R6's register-batched load stream (proven best: 7xLDG.128 front batch,
// MLP=7) with launch_bounds(256,7): reg cap 36 -> 7 blocks/SM = 56 warps
// (+17% vs R6's 48) at unchanged per-warp MLP. Address math minimized so the
// batch fits: single pre-offset base pointer, immediate-offset loads, all
// phase-2 index math deferred past the loads. cp.async experiment (R7)
// reverted: LDGSTS 8cyc issue + smem round-trip lost to plain LDG.

#define CCH    2048
#define HW     784
#define TILE_C 8
#define ACC_STRIDE 57    // odd stride: conflict-free transposed readout
#define STG_STRIDE 200   // per-warp stage stride

__global__ __launch_bounds__(256, 7)
void upp_pool_kernel(const float* __restrict__ x, float* __restrict__ out) {
    __shared__ float stage[8 * STG_STRIDE];     // 6400 B
    __shared__ float acc[TILE_C * ACC_STRIDE];  // 1824 B

    const int tid  = threadIdx.x;
    const int warp = tid >> 5;     // = c_local: one channel per warp
    const int lane = tid & 31;

    // Single address: base + lane, loads use immediate offsets only.
    const float4* __restrict__ plane =
        reinterpret_cast<const float4*>(
            x + ((size_t)(blockIdx.y * CCH + blockIdx.x * TILE_C + warp)) * HW)
        + lane;

    // Phase 1: front-batch ALL 7 LDG.128 (MLP=7). q = lane + 32k.
    const float4 v0 = plane[0];
    const float4 v1 = plane[32];
    const float4 v2 = plane[64];
    const float4 v3 = plane[96];
    const float4 v4 = plane[128];
    const float4 v5 = plane[160];
    float4 v6 = make_float4(0.f, 0.f, 0.f, 0.f);
    if (lane < 4) v6 = plane[192];

    // Horizontal partials -> per-warp stage (plain STS, conflict-free)
    const int wbase = warp * STG_STRIDE + lane;
    stage[wbase +   0] = (v0.x + v0.y + v0.z + v0.w) * 0.0625f;
    stage[wbase +  32] = (v1.x + v1.y + v1.z + v1.w) * 0.0625f;
    stage[wbase +  64] = (v2.x + v2.y + v2.z + v2.w) * 0.0625f;
    stage[wbase +  96] = (v3.x + v3.y + v3.z + v3.w) * 0.0625f;
    stage[wbase + 128] = (v4.x + v4.y + v4.z + v4.w) * 0.0625f;
    stage[wbase + 160] = (v5.x + v5.y + v5.z + v5.w) * 0.0625f;
    if (lane < 4)
        stage[wbase + 192] = (v6.x + v6.y + v6.z + v6.w) * 0.0625f;
    __syncwarp();

    // Phase 2: vertical reduce over 4 rows per bin (warp-local, no atomics).
    {
        const int o0 = warp * STG_STRIDE + 28 * (lane / 7) + (lane % 7);
        acc[warp * ACC_STRIDE + lane] =
            stage[o0] + stage[o0 + 7] + stage[o0 + 14] + stage[o0 + 21];
    }
    if (lane < 17) {
        const int b1 = lane + 32;
        const int o1 = warp * STG_STRIDE + 28 * (b1 / 7) + (b1 % 7);
        acc[warp * ACC_STRIDE + b1] =
            stage[o1] + stage[o1 + 7] + stage[o1 + 14] + stage[o1 + 21];
    }
    __syncthreads();

    // out[b, p, c0+c] = acc[c*57 + p]; 8 contiguous floats per p-row
    float* __restrict__ ob =
        out + (size_t)blockIdx.y * 49 * CCH + blockIdx.x * TILE_C;
    #pragma unroll
    for (int i = tid; i < 49 * TILE_C; i += 256) {
        const int p = i >> 3;              // 0..48
        const int c = i & (TILE_C - 1);    // 0..7
        ob[p * CCH + c] = acc[c * ACC_STRIDE + p];
    }
}

extern "C" void kernel_launch(void* const* d_in, const int* in_sizes, int n_in,
                              void* d_out, int out_size) {
    const float* x = (const float*)d_in[0];
    float* out = (float*)d_out;
    dim3 grid(CCH / TILE_C, 32);   // (256, 32) = 8192 short blocks
    upp_pool_kernel<<<grid, 256>>>(x, out);
}

// round 9
// speedup vs baseline: 1.0653x; 1.0481x over previous
#include <cuda_runtime.h>
#include <cuda_bf16.h>
#include <cstdint>

// adaptive_avg_pool2d(x[32,2048,28,28], 7) -> out[32,49,2048]
// linspace(0,28,8) = 0,4,...,28 => exact uniform 4x4 windows.
//
// R9 = R6 (best: 33.2us kernel, DRAM 82%, regs 38, MLP=7 batch, 48 warps/SM,
// 8192 short blocks) + streaming cache hints. All input is touch-once and all
// output write-once: __ldcs (evict-first) on the 7 batched LDG.128 and __stcs
// on output STG let L2 evict streaming sectors immediately, cutting LTS
// queue contention. Same instruction count/regs -> batch preserved.
// R7 (cp.async) and R8 (reg cap 36) both regressed and are reverted.

#define CCH    2048
#define HW     784
#define TILE_C 8
#define ACC_STRIDE 57    // odd stride: conflict-free transposed readout
#define STG_STRIDE 200   // per-warp stage stride

__global__ __launch_bounds__(256, 6)
void upp_pool_kernel(const float* __restrict__ x, float* __restrict__ out) {
    __shared__ float stage[8 * STG_STRIDE];     // 6400 B
    __shared__ float acc[TILE_C * ACC_STRIDE];  // 1824 B

    const int tid  = threadIdx.x;
    const int warp = tid >> 5;     // = c_local: one channel per warp
    const int lane = tid & 31;

    const float4* __restrict__ plane =
        reinterpret_cast<const float4*>(
            x + ((size_t)(blockIdx.y * CCH + blockIdx.x * TILE_C + warp)) * HW)
        + lane;

    // Phase 1: front-batch ALL 7 LDG.128 (MLP=7), streaming (evict-first).
    const float4 v0 = __ldcs(plane +   0);
    const float4 v1 = __ldcs(plane +  32);
    const float4 v2 = __ldcs(plane +  64);
    const float4 v3 = __ldcs(plane +  96);
    const float4 v4 = __ldcs(plane + 128);
    const float4 v5 = __ldcs(plane + 160);
    float4 v6 = make_float4(0.f, 0.f, 0.f, 0.f);
    if (lane < 4) v6 = __ldcs(plane + 192);

    // Horizontal partials -> per-warp stage (plain STS, conflict-free)
    const int wbase = warp * STG_STRIDE + lane;
    stage[wbase +   0] = (v0.x + v0.y + v0.z + v0.w) * 0.0625f;
    stage[wbase +  32] = (v1.x + v1.y + v1.z + v1.w) * 0.0625f;
    stage[wbase +  64] = (v2.x + v2.y + v2.z + v2.w) * 0.0625f;
    stage[wbase +  96] = (v3.x + v3.y + v3.z + v3.w) * 0.0625f;
    stage[wbase + 128] = (v4.x + v4.y + v4.z + v4.w) * 0.0625f;
    stage[wbase + 160] = (v5.x + v5.y + v5.z + v5.w) * 0.0625f;
    if (lane < 4)
        stage[wbase + 192] = (v6.x + v6.y + v6.z + v6.w) * 0.0625f;
    __syncwarp();

    // Phase 2: vertical reduce over 4 rows per bin (warp-local, no atomics).
    {
        const int o0 = warp * STG_STRIDE + 28 * (lane / 7) + (lane % 7);
        acc[warp * ACC_STRIDE + lane] =
            stage[o0] + stage[o0 + 7] + stage[o0 + 14] + stage[o0 + 21];
    }
    if (lane < 17) {
        const int b1 = lane + 32;
        const int o1 = warp * STG_STRIDE + 28 * (b1 / 7) + (b1 % 7);
        acc[warp * ACC_STRIDE + b1] =
            stage[o1] + stage[o1 + 7] + stage[o1 + 14] + stage[o1 + 21];
    }
    __syncthreads();

    // out[b, p, c0+c] = acc[c*57 + p]; 8 contiguous floats per p-row,
    // streaming stores (write-once, evict-first).
    float* __restrict__ ob =
        out + (size_t)blockIdx.y * 49 * CCH + blockIdx.x * TILE_C;
    #pragma unroll
    for (int i = tid; i < 49 * TILE_C; i += 256) {
        const int p = i >> 3;              // 0..48
        const int c = i & (TILE_C - 1);    // 0..7
        __stcs(&ob[p * CCH + c], acc[c * ACC_STRIDE + p]);
    }
}

extern "C" void kernel_launch(void* const* d_in, const int* in_sizes, int n_in,
                              void* d_out, int out_size) {
    const float* x = (const float*)d_in[0];
    float* out = (float*)d_out;
    dim3 grid(CCH / TILE_C, 32);   // (256, 32) = 8192 short blocks
    upp_pool_kernel<<<grid, 256>>>(x, out);
}

// round 10
// speedup vs baseline: 1.1298x; 1.0606x over previous
#include <cuda_runtime.h>
#include <cuda_bf16.h>
#include <cstdint>

// adaptive_avg_pool2d(x[32,2048,28,28], 7) -> out[32,49,2048]
// linspace(0,28,8) = 0,4,...,28 => exact uniform 4x4 windows.
//
// R10 = R9 (best: 32.9us kernel, LTS-cap-bound at ~6.6 TB/s effective) +
// issue-side polish:
//  - deferred scaling: phase 1 stores raw 4-sums (no FMUL in the load->STS
//    chain); single *0.0625 at phase 2 output.
//  - loop-free writeout: threads 0..195 each emit one STG.64 (49 p-rows x
//    4 float2), replacing the 2-iteration scalar store loop.
// Core structure frozen: 7xLDG.128 front batch (MLP=7), __ldcs/__stcs,
// 48 warps/SM (launch_bounds(256,6)), 8192 short blocks.

#define CCH    2048
#define HW     784
#define TILE_C 8
#define ACC_STRIDE 57    // odd stride: conflict-free transposed readout
#define STG_STRIDE 200   // per-warp stage stride

__global__ __launch_bounds__(256, 6)
void upp_pool_kernel(const float* __restrict__ x, float* __restrict__ out) {
    __shared__ float stage[8 * STG_STRIDE];     // 6400 B
    __shared__ float acc[TILE_C * ACC_STRIDE];  // 1824 B

    const int tid  = threadIdx.x;
    const int warp = tid >> 5;     // = c_local: one channel per warp
    const int lane = tid & 31;

    const float4* __restrict__ plane =
        reinterpret_cast<const float4*>(
            x + ((size_t)(blockIdx.y * CCH + blockIdx.x * TILE_C + warp)) * HW)
        + lane;

    // Phase 1: front-batch ALL 7 LDG.128 (MLP=7), streaming (evict-first).
    const float4 v0 = __ldcs(plane +   0);
    const float4 v1 = __ldcs(plane +  32);
    const float4 v2 = __ldcs(plane +  64);
    const float4 v3 = __ldcs(plane +  96);
    const float4 v4 = __ldcs(plane + 128);
    const float4 v5 = __ldcs(plane + 160);
    float4 v6 = make_float4(0.f, 0.f, 0.f, 0.f);
    if (lane < 4) v6 = __ldcs(plane + 192);

    // Raw horizontal 4-sums -> per-warp stage (scale deferred to phase 2)
    const int wbase = warp * STG_STRIDE + lane;
    stage[wbase +   0] = (v0.x + v0.y) + (v0.z + v0.w);
    stage[wbase +  32] = (v1.x + v1.y) + (v1.z + v1.w);
    stage[wbase +  64] = (v2.x + v2.y) + (v2.z + v2.w);
    stage[wbase +  96] = (v3.x + v3.y) + (v3.z + v3.w);
    stage[wbase + 128] = (v4.x + v4.y) + (v4.z + v4.w);
    stage[wbase + 160] = (v5.x + v5.y) + (v5.z + v5.w);
    if (lane < 4)
        stage[wbase + 192] = (v6.x + v6.y) + (v6.z + v6.w);
    __syncwarp();

    // Phase 2: vertical reduce over 4 rows per bin; single scale at the end.
    {
        const int o0 = warp * STG_STRIDE + 28 * (lane / 7) + (lane % 7);
        acc[warp * ACC_STRIDE + lane] =
            ((stage[o0] + stage[o0 + 7]) +
             (stage[o0 + 14] + stage[o0 + 21])) * 0.0625f;
    }
    if (lane < 17) {
        const int b1 = lane + 32;
        const int o1 = warp * STG_STRIDE + 28 * (b1 / 7) + (b1 % 7);
        acc[warp * ACC_STRIDE + b1] =
            ((stage[o1] + stage[o1 + 7]) +
             (stage[o1 + 14] + stage[o1 + 21])) * 0.0625f;
    }
    __syncthreads();

    // Writeout, loop-free: 49 p-rows x 8 channels = 196 STG.64.
    // Thread t (<196): p = t/4, channel pair c = 2*(t&3).
    if (tid < 196) {
        const int p = tid >> 2;
        const int c = (tid & 3) * 2;
        const float2 w = make_float2(acc[c * ACC_STRIDE + p],
                                     acc[(c + 1) * ACC_STRIDE + p]);
        float2* __restrict__ ob = reinterpret_cast<float2*>(
            out + (size_t)blockIdx.y * 49 * CCH + blockIdx.x * TILE_C
                + p * CCH + c);
        __stcs(ob, w);
    }
}

extern "C" void kernel_launch(void* const* d_in, const int* in_sizes, int n_in,
                              void* d_out, int out_size) {
    const float* x = (const float*)d_in[0];
    float* out = (float*)d_out;
    dim3 grid(CCH / TILE_C, 32);   // (256, 32) = 8192 short blocks
    upp_pool_kernel<<<grid, 256>>>(x, out);
}